// round 7
// baseline (speedup 1.0000x reference)
#include <cuda_runtime.h>
#include <math.h>
#include <stdint.h>
#include <mma.h>

using namespace nvcuda;

#define F 128
#define NMAX 100000
#define EMAX 1600000
#define BGR 8
#define CH 40
#define CAPD 96
#define BKP 36

// ---------------- device scratch ----------------
__device__ float g_y[NMAX * F];
__device__ float g_aggr[NMAX * F];
__device__ float g_h1[NMAX * F];
__device__ float g_h2[80000 * F];
__device__ int   g_eA[2 * EMAX];
__device__ int   g_eB[2 * EMAX];
__device__ int   g_deg[NMAX];
__device__ int   g_bkt[NMAX * CAPD];
__device__ float g_s[NMAX];
__device__ int   g_newpos[NMAX + 1];
__device__ int   g_gidx[80000];
__device__ float g_tanhv[80000];
__device__ unsigned g_thr[BGR];
__device__ int   g_needeq[BGR];
__device__ int   g_cnt[BGR];
__device__ int   g_eqcnt[BGR];
__device__ float g_z[BGR * 2 * F];
__device__ float g_part[BGR * CH * 2 * F];

__device__ __forceinline__ unsigned ordkey(float f) {
    unsigned u = __float_as_uint(f);
    return (u & 0x80000000u) ? ~u : (u | 0x80000000u);
}

// ---------------- wmma TF32 GEMM (2-term split, 3 MMA terms) ----------------
// C[M x 128] = relu(A1 @ W[:, :128]^T (+ A2 @ W[:,128:]^T) + bias)
template <int KPARTS>
__global__ __launch_bounds__(256)
void k_gemm_mma(const float* __restrict__ A1, const float* __restrict__ A2,
                const float* __restrict__ W, const float* __restrict__ bias,
                float* __restrict__ C, int M)
{
    __shared__ float sA[128][BKP];
    __shared__ float sW[128][BKP];
    __shared__ float stage[8][256];

    const int tid = threadIdx.x;
    const int wid = tid >> 5, lane = tid & 31;
    const int warp_m = wid & 1;          // 0..1 -> 64 rows each
    const int warp_n = wid >> 1;         // 0..3 -> 32 cols each
    const int r0 = blockIdx.x * 128;
    const int K = KPARTS * 128;
    const int NCH = KPARTS * 4;

    // smem load coords: each thread loads 16 consecutive floats of one row
    const int lrow = tid >> 1;           // 0..127
    const int lcol = (tid & 1) * 16;     // 0 or 16

    wmma::fragment<wmma::accumulator, 16, 16, 8, float> acc[4][2];
#pragma unroll
    for (int i = 0; i < 4; i++)
#pragma unroll
        for (int j = 0; j < 2; j++) wmma::fill_fragment(acc[i][j], 0.f);

    for (int c = 0; c < NCH; ++c) {
        const float* Asrc = A1;
        int acol = c * 32;
        if (KPARTS == 2 && c >= 4) { Asrc = A2; acol = (c - 4) * 32; }

        // load A tile 128x32 and W tile 128x32
        {
            int gr = r0 + lrow;
#pragma unroll
            for (int j = 0; j < 4; j++) {
                float4 v = (gr < M) ? *(const float4*)(Asrc + (size_t)gr * F + acol + lcol + j * 4)
                                    : make_float4(0.f, 0.f, 0.f, 0.f);
                *(float4*)&sA[lrow][lcol + j * 4] = v;
            }
#pragma unroll
            for (int j = 0; j < 4; j++) {
                float4 v = *(const float4*)(W + (size_t)lrow * K + c * 32 + lcol + j * 4);
                *(float4*)&sW[lrow][lcol + j * 4] = v;
            }
        }
        __syncthreads();

#pragma unroll
        for (int k8 = 0; k8 < 4; k8++) {
            // load + split A fragments (4 m-tiles)
            wmma::fragment<wmma::matrix_a, 16, 16, 8, wmma::precision::tf32, wmma::row_major> ahi[4], alo[4];
#pragma unroll
            for (int wm = 0; wm < 4; wm++) {
                wmma::load_matrix_sync(ahi[wm], &sA[warp_m * 64 + wm * 16][k8 * 8], BKP);
#pragma unroll
                for (int e = 0; e < ahi[wm].num_elements; e++) {
                    float orig = ahi[wm].x[e];
                    float hi = wmma::__float_to_tf32(orig);
                    ahi[wm].x[e] = hi;
                    alo[wm].x[e] = wmma::__float_to_tf32(orig - hi);
                }
            }
            // load + split B fragments (2 n-tiles)
            wmma::fragment<wmma::matrix_b, 16, 16, 8, wmma::precision::tf32, wmma::col_major> bhi[2], blo[2];
#pragma unroll
            for (int wn = 0; wn < 2; wn++) {
                wmma::load_matrix_sync(bhi[wn], &sW[warp_n * 32 + wn * 16][k8 * 8], BKP);
#pragma unroll
                for (int e = 0; e < bhi[wn].num_elements; e++) {
                    float orig = bhi[wn].x[e];
                    float hi = wmma::__float_to_tf32(orig);
                    bhi[wn].x[e] = hi;
                    blo[wn].x[e] = wmma::__float_to_tf32(orig - hi);
                }
            }
#pragma unroll
            for (int wm = 0; wm < 4; wm++)
#pragma unroll
                for (int wn = 0; wn < 2; wn++) {
                    wmma::mma_sync(acc[wm][wn], ahi[wm], bhi[wn], acc[wm][wn]);
                    wmma::mma_sync(acc[wm][wn], ahi[wm], blo[wn], acc[wm][wn]);
                    wmma::mma_sync(acc[wm][wn], alo[wm], bhi[wn], acc[wm][wn]);
                }
        }
        __syncthreads();
    }

    // epilogue: stage each 16x16 frag in smem, apply bias+relu, write out
#pragma unroll
    for (int wm = 0; wm < 4; wm++)
#pragma unroll
        for (int wn = 0; wn < 2; wn++) {
            wmma::store_matrix_sync(stage[wid], acc[wm][wn], 16, wmma::mem_row_major);
            __syncwarp();
            int m0 = warp_m * 64 + wm * 16;
            int n0 = warp_n * 32 + wn * 16;
#pragma unroll
            for (int e = 0; e < 8; e++) {
                int idx = e * 32 + lane;
                int row = idx >> 4, col = idx & 15;
                int gr = r0 + m0 + row;
                if (gr < M) {
                    int gc = n0 + col;
                    float v = stage[wid][idx] + (bias ? bias[gc] : 0.f);
                    C[(size_t)gr * F + gc] = fmaxf(v, 0.f);
                }
            }
            __syncwarp();
        }
}

// ---------------- CSR-bucket build ----------------
__global__ void k_zerodeg(int M)
{
    int i = blockIdx.x * blockDim.x + threadIdx.x;
    if (i < M) g_deg[i] = 0;
}

__global__ void k_bucket(const int* __restrict__ esrc, const int* __restrict__ edst,
                         int E, int M)
{
    int t = blockIdx.x * blockDim.x + threadIdx.x;
    int half = E >> 1;
    if (t >= half) return;
#pragma unroll
    for (int q = 0; q < 2; q++) {
        int e = t + q * half;
        int d = edst[e];
        if (d >= M) continue;
        int s = esrc[e];
        int pos = atomicAdd(&g_deg[d], 1);
        if (pos < CAPD) g_bkt[(size_t)d * CAPD + pos] = s;
    }
}

// ---------------- gather-max: warp per dst node ----------------
__global__ void k_aggr(const float* __restrict__ y, float* __restrict__ aggr, int M)
{
    int warp = blockIdx.x * (blockDim.x >> 5) + (threadIdx.x >> 5);
    int lane = threadIdx.x & 31;
    if (warp >= M) return;
    int dv = g_deg[warp];
    if (dv > CAPD) dv = CAPD;
    const int* b = g_bkt + (size_t)warp * CAPD;
    float4 acc = ((const float4*)(y + (size_t)warp * F))[lane];
    int i = 0;
    for (; i + 1 < dv; i += 2) {
        int s0 = b[i], s1 = b[i + 1];
        float4 t0 = ((const float4*)(y + (size_t)s0 * F))[lane];
        float4 t1 = ((const float4*)(y + (size_t)s1 * F))[lane];
        acc.x = fmaxf(acc.x, fmaxf(t0.x, t1.x));
        acc.y = fmaxf(acc.y, fmaxf(t0.y, t1.y));
        acc.z = fmaxf(acc.z, fmaxf(t0.z, t1.z));
        acc.w = fmaxf(acc.w, fmaxf(t0.w, t1.w));
    }
    if (i < dv) {
        int s0 = b[i];
        float4 t0 = ((const float4*)(y + (size_t)s0 * F))[lane];
        acc.x = fmaxf(acc.x, t0.x);
        acc.y = fmaxf(acc.y, t0.y);
        acc.z = fmaxf(acc.z, t0.z);
        acc.w = fmaxf(acc.w, t0.w);
    }
    ((float4*)(aggr + (size_t)warp * F))[lane] = acc;
}

// ---------------- scores (wnorm fused) ----------------
__global__ void k_scores(const float* __restrict__ h, const float* __restrict__ w, int M)
{
    __shared__ float s_inv;
    int lane = threadIdx.x & 31;
    if (threadIdx.x < 32) {
        float4 b0 = ((const float4*)w)[lane];
        float sq = b0.x * b0.x + b0.y * b0.y + b0.z * b0.z + b0.w * b0.w;
        for (int o = 16; o > 0; o >>= 1) sq += __shfl_down_sync(0xffffffffu, sq, o);
        if (lane == 0) s_inv = rsqrtf(sq);
    }
    __syncthreads();
    int warp = blockIdx.x * (blockDim.x >> 5) + (threadIdx.x >> 5);
    if (warp >= M) return;
    float4 a = ((const float4*)(h + (size_t)warp * F))[lane];
    float4 b = ((const float4*)w)[lane];
    float d = a.x * b.x + a.y * b.y + a.z * b.z + a.w * b.w;
    for (int o = 16; o > 0; o >>= 1) d += __shfl_down_sync(0xffffffffu, d, o);
    if (lane == 0) g_s[warp] = d * s_inv;
}

// ---------------- per-graph exact radix select (1024 threads) ----------------
__global__ __launch_bounds__(1024)
void k_select(int n, int kk)
{
    int g = blockIdx.x;
    const float* sg = g_s + (size_t)g * n;
    __shared__ unsigned hist[256];
    __shared__ unsigned s_prefix, s_mask;
    __shared__ int s_need;
    if (threadIdx.x == 0) { s_prefix = 0; s_mask = 0; s_need = kk; }
    __syncthreads();
    for (int pass = 0; pass < 4; ++pass) {
        int shift = 24 - 8 * pass;
        if (threadIdx.x < 256) hist[threadIdx.x] = 0;
        __syncthreads();
        unsigned pre = s_prefix, msk = s_mask;
        for (int i = threadIdx.x; i < n; i += blockDim.x) {
            unsigned key = ordkey(sg[i]);
            if ((key & msk) == pre) atomicAdd(&hist[(key >> shift) & 255], 1u);
        }
        __syncthreads();
        if (threadIdx.x == 0) {
            int need = s_need;
            unsigned cum = 0;
            for (int b = 255; b >= 0; --b) {
                unsigned h = hist[b];
                if (cum + h >= (unsigned)need) {
                    s_need = need - (int)cum;
                    s_prefix = pre | ((unsigned)b << shift);
                    s_mask = msk | (255u << shift);
                    break;
                }
                cum += h;
            }
        }
        __syncthreads();
    }
    if (threadIdx.x == 0) { g_thr[g] = s_prefix; g_needeq[g] = s_need; }
}

__global__ void k_initpool(int Msize, int Mn)
{
    int i = blockIdx.x * blockDim.x + threadIdx.x;
    if (i < Msize) g_newpos[i] = Mn;
    if (i < BGR) { g_cnt[i] = 0; g_eqcnt[i] = 0; }
}

__global__ void k_compact(int M, int n, int kk)
{
    int v = blockIdx.x * blockDim.x + threadIdx.x;
    if (v >= M) return;
    int g = v / n;
    float sv = g_s[v];
    unsigned key = ordkey(sv);
    unsigned T = g_thr[g];
    bool keep = false;
    if (key > T) keep = true;
    else if (key == T && atomicAdd(&g_eqcnt[g], 1) < g_needeq[g]) keep = true;
    if (!keep) return;
    int pos = atomicAdd(&g_cnt[g], 1);
    int j = g * kk + pos;
    g_newpos[v] = j;
    g_gidx[j] = v;
    g_tanhv[j] = tanhf(sv);
}

__global__ void k_gather(const float* __restrict__ h, float* __restrict__ xnew, int Mn)
{
    int idx = blockIdx.x * blockDim.x + threadIdx.x;
    int j = idx >> 5, q = idx & 31;
    if (j >= Mn) return;
    float t = g_tanhv[j];
    float4 v = *(const float4*)(h + (size_t)g_gidx[j] * F + q * 4);
    v.x *= t; v.y *= t; v.z *= t; v.w *= t;
    *(float4*)(xnew + (size_t)j * F + q * 4) = v;
}

__global__ void k_remap(const int* __restrict__ es, const int* __restrict__ ed,
                        int* __restrict__ eo, int E, int Mn)
{
    int i = blockIdx.x * blockDim.x + threadIdx.x;
    if (i >= E) return;
    int s = g_newpos[es[i]];
    int d = g_newpos[ed[i]];
    if (s == Mn || d == Mn) { s = Mn; d = Mn; }
    eo[i] = s;
    eo[E + i] = d;
}

// ---------------- readout ----------------
__global__ void k_rpart(const float* __restrict__ x, int kk)
{
    int g = blockIdx.x / CH, c = blockIdx.x % CH;
    int rpc = kk / CH;
    int f = threadIdx.x;  // 128
    const float* base = x + ((size_t)g * kk + (size_t)c * rpc) * F + f;
    float vmax = -3.4e38f, vsum = 0.f;
    for (int r = 0; r < rpc; r++) {
        float v = base[(size_t)r * F];
        vmax = fmaxf(vmax, v);
        vsum += v;
    }
    float* p = g_part + (size_t)blockIdx.x * 2 * F;
    p[f] = vmax;
    p[F + f] = vsum;
}

__global__ void k_rfinal(int kk)
{
    int g = blockIdx.x;
    int f = threadIdx.x;  // 256
    const float* p = g_part + (size_t)g * CH * 2 * F;
    if (f < F) {
        float m = -3.4e38f;
        for (int c = 0; c < CH; c++) m = fmaxf(m, p[c * 2 * F + f]);
        g_z[g * 2 * F + f] += m;
    } else {
        float s = 0.f;
        for (int c = 0; c < CH; c++) s += p[c * 2 * F + f];
        g_z[g * 2 * F + f] += s / (float)kk;
    }
}

__global__ void k_zeroz()
{
    int i = blockIdx.x * blockDim.x + threadIdx.x;
    if (i < BGR * 2 * F) g_z[i] = 0.f;
}

// ---------------- final MLP + sigmoid ----------------
__global__ void k_mlp(const float* __restrict__ Wl1, const float* __restrict__ bl1,
                      const float* __restrict__ Wl2, const float* __restrict__ bl2,
                      const float* __restrict__ Wl3, const float* __restrict__ bl3,
                      float* __restrict__ out)
{
    __shared__ float sz[BGR][2 * F];
    __shared__ float h1[BGR][F];
    __shared__ float h2[BGR][64];
    int t = threadIdx.x;  // 256
    for (int i = t; i < BGR * 2 * F; i += 256) ((float*)sz)[i] = g_z[i];
    __syncthreads();
    for (int o = t; o < BGR * F; o += 256) {
        int g = o >> 7, r = o & 127;
        float a = bl1[r];
        const float* wr = Wl1 + (size_t)r * 2 * F;
        for (int c = 0; c < 2 * F; c++) a += sz[g][c] * wr[c];
        h1[g][r] = fmaxf(a, 0.f);
    }
    __syncthreads();
    for (int o = t; o < BGR * 64; o += 256) {
        int g = o >> 6, r = o & 63;
        float a = bl2[r];
        const float* wr = Wl2 + (size_t)r * F;
        for (int c = 0; c < F; c++) a += h1[g][c] * wr[c];
        h2[g][r] = fmaxf(a, 0.f);
    }
    __syncthreads();
    if (t < BGR) {
        float a = bl3[0];
        for (int c = 0; c < 64; c++) a += h2[t][c] * Wl3[c];
        out[t] = 1.f / (1.f + expf(-a));
    }
}

// ---------------- orchestration ----------------
extern "C" void kernel_launch(void* const* d_in, const int* in_sizes, int n_in,
                              void* d_out, int out_size)
{
    const float* x = (const float*)d_in[0];
    const int* ei = (const int*)d_in[1];
    const float* Wlin[3] = { (const float*)d_in[2], (const float*)d_in[6], (const float*)d_in[10] };
    const float* blin[3] = { (const float*)d_in[3], (const float*)d_in[7], (const float*)d_in[11] };
    const float* Wupd[3] = { (const float*)d_in[4], (const float*)d_in[8], (const float*)d_in[12] };
    const float* wp[3]   = { (const float*)d_in[5], (const float*)d_in[9], (const float*)d_in[13] };
    const float* Wl1 = (const float*)d_in[14];
    const float* bl1 = (const float*)d_in[15];
    const float* Wl2 = (const float*)d_in[16];
    const float* bl2 = (const float*)d_in[17];
    const float* Wl3 = (const float*)d_in[18];
    const float* bl3 = (const float*)d_in[19];

    float *yb, *ag, *h1p, *h2p;
    int *eA, *eB;
    cudaGetSymbolAddress((void**)&yb, g_y);
    cudaGetSymbolAddress((void**)&ag, g_aggr);
    cudaGetSymbolAddress((void**)&h1p, g_h1);
    cudaGetSymbolAddress((void**)&h2p, g_h2);
    cudaGetSymbolAddress((void**)&eA, g_eA);
    cudaGetSymbolAddress((void**)&eB, g_eB);

    const int Ms[3] = { 100000, 80000, 64000 };
    const int kks[3] = { 10000, 8000, 6400 };

    k_zeroz<<<8, 256>>>();

    const float* hin = x;
    const int* es = ei;
    const int* ed = ei + EMAX;

    for (int st = 0; st < 3; ++st) {
        int M = Ms[st];
        int gridG = (M + 127) / 128;

        k_gemm_mma<1><<<gridG, 256>>>(hin, nullptr, Wlin[st], blin[st], yb, M);
        k_zerodeg<<<(M + 255) / 256, 256>>>(M);
        k_bucket<<<(EMAX / 2 + 255) / 256, 256>>>(es, ed, EMAX, M);
        k_aggr<<<(M + 7) / 8, 256>>>(yb, ag, M);
        k_gemm_mma<2><<<gridG, 256>>>(ag, hin, Wupd[st], nullptr, h1p, M);

        int kk = kks[st], n = M / BGR, Mn = BGR * kk;
        k_scores<<<(M + 3) / 4, 128>>>(h1p, wp[st], M);
        k_select<<<BGR, 1024>>>(n, kk);
        k_initpool<<<(M + 1 + 255) / 256, 256>>>(M + 1, Mn);
        k_compact<<<(M + 255) / 256, 256>>>(M, n, kk);
        k_gather<<<(Mn * 32 + 255) / 256, 256>>>(h1p, h2p, Mn);
        if (st < 2) {
            int* eo = (st == 0) ? eA : eB;
            k_remap<<<(EMAX + 255) / 256, 256>>>(es, ed, eo, EMAX, Mn);
            es = eo;
            ed = eo + EMAX;
        }

        k_rpart<<<BGR * CH, 128>>>(h2p, kk);
        k_rfinal<<<BGR, 256>>>(kk);

        hin = h2p;
    }

    k_mlp<<<1, 256>>>(Wl1, bl1, Wl2, bl2, Wl3, bl3, (float*)d_out);
}

// round 8
// speedup vs baseline: 1.1480x; 1.1480x over previous
#include <cuda_runtime.h>
#include <math.h>
#include <stdint.h>

#define F 128
#define NMAX 100000
#define EMAX 1600000
#define BGR 8
#define CH 40
#define CAPD 96

// ---------------- device scratch ----------------
__device__ float g_y[NMAX * F];
__device__ float g_aggr[NMAX * F];
__device__ float g_h1[NMAX * F];
__device__ float g_h2[80000 * F];
__device__ int   g_eA[2 * EMAX];
__device__ int   g_eB[2 * EMAX];
__device__ int   g_deg[NMAX];
__device__ int   g_bkt[NMAX * CAPD];
__device__ float g_s[NMAX];
__device__ int   g_newpos[NMAX + 1];
__device__ int   g_gidx[80000];
__device__ float g_tanhv[80000];
__device__ unsigned g_thr[BGR];
__device__ int   g_needeq[BGR];
__device__ int   g_cnt[BGR];
__device__ int   g_eqcnt[BGR];
__device__ float g_z[BGR * 2 * F];
__device__ float g_part[BGR * CH * 2 * F];

__device__ __forceinline__ unsigned ordkey(float f) {
    unsigned u = __float_as_uint(f);
    return (u & 0x80000000u) ? ~u : (u | 0x80000000u);
}

// ---------------- GEMM (best known scalar, R4): C = relu(A1@W1^T (+A2@W2^T) + bias)
template <int KPARTS>
__global__ __launch_bounds__(256)
void k_gemm(const float* __restrict__ A1, const float* __restrict__ A2,
            const float* __restrict__ W, const float* __restrict__ bias,
            float* __restrict__ C, int M)
{
    __shared__ float sA[2][16][132];
    __shared__ float sB[2][16][132];
    const int tid = threadIdx.x;
    const int tx = tid & 15, ty = tid >> 4;
    const int r0 = blockIdx.x * 128;
    const int K = KPARTS * 128;
    const int NSTEP = KPARTS * 8;

    const int rowA0 = tid >> 2,          kcA0 = (tid & 3) * 4;
    const int rowA1 = (tid + 256) >> 2,  kcA1 = ((tid + 256) & 3) * 4;

    float acc[8][8];
#pragma unroll
    for (int i = 0; i < 8; i++)
#pragma unroll
        for (int j = 0; j < 8; j++) acc[i][j] = 0.f;

    float4 va0, va1, vb0, vb1;

    auto loadG = [&](int kk0) {
        const float* Asrc = A1; int acol = kk0;
        if (KPARTS == 2 && kk0 >= 128) { Asrc = A2; acol = kk0 - 128; }
        int gr0 = r0 + rowA0, gr1 = r0 + rowA1;
        va0 = make_float4(0.f, 0.f, 0.f, 0.f);
        va1 = make_float4(0.f, 0.f, 0.f, 0.f);
        if (gr0 < M) va0 = *(const float4*)(Asrc + (size_t)gr0 * F + acol + kcA0);
        if (gr1 < M) va1 = *(const float4*)(Asrc + (size_t)gr1 * F + acol + kcA1);
        vb0 = *(const float4*)(W + (size_t)rowA0 * K + kk0 + kcA0);
        vb1 = *(const float4*)(W + (size_t)rowA1 * K + kk0 + kcA1);
    };
    auto storeS = [&](int buf) {
        sA[buf][kcA0 + 0][rowA0] = va0.x; sA[buf][kcA0 + 1][rowA0] = va0.y;
        sA[buf][kcA0 + 2][rowA0] = va0.z; sA[buf][kcA0 + 3][rowA0] = va0.w;
        sA[buf][kcA1 + 0][rowA1] = va1.x; sA[buf][kcA1 + 1][rowA1] = va1.y;
        sA[buf][kcA1 + 2][rowA1] = va1.z; sA[buf][kcA1 + 3][rowA1] = va1.w;
        sB[buf][kcA0 + 0][rowA0] = vb0.x; sB[buf][kcA0 + 1][rowA0] = vb0.y;
        sB[buf][kcA0 + 2][rowA0] = vb0.z; sB[buf][kcA0 + 3][rowA0] = vb0.w;
        sB[buf][kcA1 + 0][rowA1] = vb1.x; sB[buf][kcA1 + 1][rowA1] = vb1.y;
        sB[buf][kcA1 + 2][rowA1] = vb1.z; sB[buf][kcA1 + 3][rowA1] = vb1.w;
    };

    loadG(0);
    storeS(0);
    __syncthreads();

    int buf = 0;
    for (int s = 0; s < NSTEP; ++s) {
        if (s + 1 < NSTEP) loadG((s + 1) * 16);
#pragma unroll
        for (int k = 0; k < 16; k++) {
            float4 a0 = *(const float4*)&sA[buf][k][ty * 8];
            float4 a1 = *(const float4*)&sA[buf][k][ty * 8 + 4];
            float4 b0 = *(const float4*)&sB[buf][k][tx * 8];
            float4 b1 = *(const float4*)&sB[buf][k][tx * 8 + 4];
            float ra[8] = { a0.x, a0.y, a0.z, a0.w, a1.x, a1.y, a1.z, a1.w };
            float rb[8] = { b0.x, b0.y, b0.z, b0.w, b1.x, b1.y, b1.z, b1.w };
#pragma unroll
            for (int i = 0; i < 8; i++)
#pragma unroll
                for (int j = 0; j < 8; j++)
                    acc[i][j] = fmaf(ra[i], rb[j], acc[i][j]);
        }
        if (s + 1 < NSTEP) {
            storeS(buf ^ 1);
            __syncthreads();
            buf ^= 1;
        }
    }

#pragma unroll
    for (int i = 0; i < 8; i++) {
        int gr = r0 + ty * 8 + i;
        if (gr >= M) continue;
#pragma unroll
        for (int j = 0; j < 8; j++) {
            int gc = tx * 8 + j;
            float v = acc[i][j] + (bias ? bias[gc] : 0.f);
            C[(size_t)gr * F + gc] = fmaxf(v, 0.f);
        }
    }
}

// ---------------- CSR-bucket build ----------------
__global__ void k_zerodeg(int M)
{
    int i = blockIdx.x * blockDim.x + threadIdx.x;
    if (i < M) g_deg[i] = 0;
}

__global__ void k_bucket(const int* __restrict__ esrc, const int* __restrict__ edst,
                         int E, int M)
{
    int t = blockIdx.x * blockDim.x + threadIdx.x;
    int half = E >> 1;
    if (t >= half) return;
#pragma unroll
    for (int q = 0; q < 2; q++) {
        int e = t + q * half;
        int d = edst[e];
        if (d >= M) continue;
        int s = esrc[e];
        int pos = atomicAdd(&g_deg[d], 1);
        if (pos < CAPD) g_bkt[(size_t)d * CAPD + pos] = s;
    }
}

// ---------------- gather-max: warp per dst node ----------------
__global__ void k_aggr(const float* __restrict__ y, float* __restrict__ aggr, int M)
{
    int warp = blockIdx.x * (blockDim.x >> 5) + (threadIdx.x >> 5);
    int lane = threadIdx.x & 31;
    if (warp >= M) return;
    int dv = g_deg[warp];
    if (dv > CAPD) dv = CAPD;
    const int* b = g_bkt + (size_t)warp * CAPD;
    float4 acc = ((const float4*)(y + (size_t)warp * F))[lane];
    int i = 0;
    for (; i + 1 < dv; i += 2) {
        int s0 = b[i], s1 = b[i + 1];
        float4 t0 = ((const float4*)(y + (size_t)s0 * F))[lane];
        float4 t1 = ((const float4*)(y + (size_t)s1 * F))[lane];
        acc.x = fmaxf(acc.x, fmaxf(t0.x, t1.x));
        acc.y = fmaxf(acc.y, fmaxf(t0.y, t1.y));
        acc.z = fmaxf(acc.z, fmaxf(t0.z, t1.z));
        acc.w = fmaxf(acc.w, fmaxf(t0.w, t1.w));
    }
    if (i < dv) {
        int s0 = b[i];
        float4 t0 = ((const float4*)(y + (size_t)s0 * F))[lane];
        acc.x = fmaxf(acc.x, t0.x);
        acc.y = fmaxf(acc.y, t0.y);
        acc.z = fmaxf(acc.z, t0.z);
        acc.w = fmaxf(acc.w, t0.w);
    }
    ((float4*)(aggr + (size_t)warp * F))[lane] = acc;
}

// ---------------- scores (wnorm fused) ----------------
__global__ void k_scores(const float* __restrict__ h, const float* __restrict__ w, int M)
{
    __shared__ float s_inv;
    int lane = threadIdx.x & 31;
    if (threadIdx.x < 32) {
        float4 b0 = ((const float4*)w)[lane];
        float sq = b0.x * b0.x + b0.y * b0.y + b0.z * b0.z + b0.w * b0.w;
        for (int o = 16; o > 0; o >>= 1) sq += __shfl_down_sync(0xffffffffu, sq, o);
        if (lane == 0) s_inv = rsqrtf(sq);
    }
    __syncthreads();
    int warp = blockIdx.x * (blockDim.x >> 5) + (threadIdx.x >> 5);
    if (warp >= M) return;
    float4 a = ((const float4*)(h + (size_t)warp * F))[lane];
    float4 b = ((const float4*)w)[lane];
    float d = a.x * b.x + a.y * b.y + a.z * b.z + a.w * b.w;
    for (int o = 16; o > 0; o >>= 1) d += __shfl_down_sync(0xffffffffu, d, o);
    if (lane == 0) g_s[warp] = d * s_inv;
}

// ---------------- per-graph exact radix select (also zeroes pool counters) ----------------
__global__ __launch_bounds__(1024)
void k_select(int n, int kk)
{
    int g = blockIdx.x;
    const float* sg = g_s + (size_t)g * n;
    __shared__ unsigned hist[256];
    __shared__ unsigned s_prefix, s_mask;
    __shared__ int s_need;
    if (threadIdx.x == 0) { s_prefix = 0; s_mask = 0; s_need = kk; }
    __syncthreads();
    for (int pass = 0; pass < 4; ++pass) {
        int shift = 24 - 8 * pass;
        if (threadIdx.x < 256) hist[threadIdx.x] = 0;
        __syncthreads();
        unsigned pre = s_prefix, msk = s_mask;
        for (int i = threadIdx.x; i < n; i += blockDim.x) {
            unsigned key = ordkey(sg[i]);
            if ((key & msk) == pre) atomicAdd(&hist[(key >> shift) & 255], 1u);
        }
        __syncthreads();
        if (threadIdx.x == 0) {
            int need = s_need;
            unsigned cum = 0;
            for (int b = 255; b >= 0; --b) {
                unsigned h = hist[b];
                if (cum + h >= (unsigned)need) {
                    s_need = need - (int)cum;
                    s_prefix = pre | ((unsigned)b << shift);
                    s_mask = msk | (255u << shift);
                    break;
                }
                cum += h;
            }
        }
        __syncthreads();
    }
    if (threadIdx.x == 0) {
        g_thr[g] = s_prefix; g_needeq[g] = s_need;
        g_cnt[g] = 0; g_eqcnt[g] = 0;
    }
}

// ---------------- compact: writes newpos for ALL nodes (initpool fused) ----------------
__global__ void k_compact(int M, int n, int kk, int Mn)
{
    int v = blockIdx.x * blockDim.x + threadIdx.x;
    if (v > M) return;
    if (v == M) { g_newpos[M] = Mn; return; }   // dummy slot
    int g = v / n;
    float sv = g_s[v];
    unsigned key = ordkey(sv);
    unsigned T = g_thr[g];
    bool keep = false;
    if (key > T) keep = true;
    else if (key == T && atomicAdd(&g_eqcnt[g], 1) < g_needeq[g]) keep = true;
    if (!keep) { g_newpos[v] = Mn; return; }
    int pos = atomicAdd(&g_cnt[g], 1);
    int j = g * kk + pos;
    g_newpos[v] = j;
    g_gidx[j] = v;
    g_tanhv[j] = tanhf(sv);
}

__global__ void k_gather(const float* __restrict__ h, float* __restrict__ xnew, int Mn)
{
    int idx = blockIdx.x * blockDim.x + threadIdx.x;
    int j = idx >> 5, q = idx & 31;
    if (j >= Mn) return;
    float t = g_tanhv[j];
    float4 v = *(const float4*)(h + (size_t)g_gidx[j] * F + q * 4);
    v.x *= t; v.y *= t; v.z *= t; v.w *= t;
    *(float4*)(xnew + (size_t)j * F + q * 4) = v;
}

__global__ void k_remap(const int* __restrict__ es, const int* __restrict__ ed,
                        int* __restrict__ eo, int E, int Mn)
{
    int i = blockIdx.x * blockDim.x + threadIdx.x;
    if (i >= E) return;
    int s = g_newpos[es[i]];
    int d = g_newpos[ed[i]];
    if (s == Mn || d == Mn) { s = Mn; d = Mn; }
    eo[i] = s;
    eo[E + i] = d;
}

// ---------------- readout ----------------
__global__ void k_rpart(const float* __restrict__ x, int kk)
{
    int g = blockIdx.x / CH, c = blockIdx.x % CH;
    int rpc = kk / CH;
    int f = threadIdx.x;  // 128
    const float* base = x + ((size_t)g * kk + (size_t)c * rpc) * F + f;
    float vmax = -3.4e38f, vsum = 0.f;
    for (int r = 0; r < rpc; r++) {
        float v = base[(size_t)r * F];
        vmax = fmaxf(vmax, v);
        vsum += v;
    }
    float* p = g_part + (size_t)blockIdx.x * 2 * F;
    p[f] = vmax;
    p[F + f] = vsum;
}

__global__ void k_rfinal(int kk, int store)
{
    int g = blockIdx.x;
    int f = threadIdx.x;  // 256
    const float* p = g_part + (size_t)g * CH * 2 * F;
    float r;
    if (f < F) {
        float m = -3.4e38f;
        for (int c = 0; c < CH; c++) m = fmaxf(m, p[c * 2 * F + f]);
        r = m;
    } else {
        float s = 0.f;
        for (int c = 0; c < CH; c++) s += p[c * 2 * F + f];
        r = s / (float)kk;
    }
    if (store) g_z[g * 2 * F + f] = r;
    else       g_z[g * 2 * F + f] += r;
}

// ---------------- final MLP + sigmoid ----------------
__global__ void k_mlp(const float* __restrict__ Wl1, const float* __restrict__ bl1,
                      const float* __restrict__ Wl2, const float* __restrict__ bl2,
                      const float* __restrict__ Wl3, const float* __restrict__ bl3,
                      float* __restrict__ out)
{
    __shared__ float sz[BGR][2 * F];
    __shared__ float h1[BGR][F];
    __shared__ float h2[BGR][64];
    int t = threadIdx.x;  // 256
    for (int i = t; i < BGR * 2 * F; i += 256) ((float*)sz)[i] = g_z[i];
    __syncthreads();
    for (int o = t; o < BGR * F; o += 256) {
        int g = o >> 7, r = o & 127;
        float a = bl1[r];
        const float* wr = Wl1 + (size_t)r * 2 * F;
        for (int c = 0; c < 2 * F; c++) a += sz[g][c] * wr[c];
        h1[g][r] = fmaxf(a, 0.f);
    }
    __syncthreads();
    for (int o = t; o < BGR * 64; o += 256) {
        int g = o >> 6, r = o & 63;
        float a = bl2[r];
        const float* wr = Wl2 + (size_t)r * F;
        for (int c = 0; c < F; c++) a += h1[g][c] * wr[c];
        h2[g][r] = fmaxf(a, 0.f);
    }
    __syncthreads();
    if (t < BGR) {
        float a = bl3[0];
        for (int c = 0; c < 64; c++) a += h2[t][c] * Wl3[c];
        out[t] = 1.f / (1.f + expf(-a));
    }
}

// ---------------- orchestration (fork/join on cudaStreamPerThread) ----------------
#define NEV 32

extern "C" void kernel_launch(void* const* d_in, const int* in_sizes, int n_in,
                              void* d_out, int out_size)
{
    const float* x = (const float*)d_in[0];
    const int* ei = (const int*)d_in[1];
    const float* Wlin[3] = { (const float*)d_in[2], (const float*)d_in[6], (const float*)d_in[10] };
    const float* blin[3] = { (const float*)d_in[3], (const float*)d_in[7], (const float*)d_in[11] };
    const float* Wupd[3] = { (const float*)d_in[4], (const float*)d_in[8], (const float*)d_in[12] };
    const float* wp[3]   = { (const float*)d_in[5], (const float*)d_in[9], (const float*)d_in[13] };
    const float* Wl1 = (const float*)d_in[14];
    const float* bl1 = (const float*)d_in[15];
    const float* Wl2 = (const float*)d_in[16];
    const float* bl2 = (const float*)d_in[17];
    const float* Wl3 = (const float*)d_in[18];
    const float* bl3 = (const float*)d_in[19];

    float *yb, *ag, *h1p, *h2p;
    int *eA, *eB;
    cudaGetSymbolAddress((void**)&yb, g_y);
    cudaGetSymbolAddress((void**)&ag, g_aggr);
    cudaGetSymbolAddress((void**)&h1p, g_h1);
    cudaGetSymbolAddress((void**)&h2p, g_h2);
    cudaGetSymbolAddress((void**)&eA, g_eA);
    cudaGetSymbolAddress((void**)&eB, g_eB);

    static cudaEvent_t ev[NEV];
    static int ev_init = 0;
    if (!ev_init) {
        for (int i = 0; i < NEV; i++)
            cudaEventCreateWithFlags(&ev[i], cudaEventDisableTiming);
        ev_init = 1;
    }
    int ei_ctr = 0;

    cudaStream_t m = 0;                    // legacy default (capture stream)
    cudaStream_t sd = cudaStreamPerThread; // side stream

    const int Ms[3] = { 100000, 80000, 64000 };
    const int kks[3] = { 10000, 8000, 6400 };

    // fork side stream off the capture stream
    cudaEventRecord(ev[ei_ctr], m);
    cudaStreamWaitEvent(sd, ev[ei_ctr], 0);
    ei_ctr++;

    const float* hin = x;
    const int* es = ei;
    const int* ed = ei + EMAX;

    int evA_prev = -1, evRP_prev = -1, evR_prev = -1;

    for (int st = 0; st < 3; ++st) {
        int M = Ms[st];
        int gridG = (M + 127) / 128;
        int kk = kks[st], n = M / BGR, Mn = BGR * kk;

        // ---- side: bucket build (overlaps gemm1)
        if (evA_prev >= 0) cudaStreamWaitEvent(sd, ev[evA_prev], 0);  // prev aggr read g_deg/g_bkt
        k_zerodeg<<<(M + 255) / 256, 256, 0, sd>>>(M);
        k_bucket<<<(EMAX / 2 + 255) / 256, 256, 0, sd>>>(es, ed, EMAX, M);
        int evB = ei_ctr; cudaEventRecord(ev[ei_ctr++], sd);

        // ---- main: SAGEConv
        k_gemm<1><<<gridG, 256, 0, m>>>(hin, nullptr, Wlin[st], blin[st], yb, M);
        cudaStreamWaitEvent(m, ev[evB], 0);
        k_aggr<<<(M + 7) / 8, 256, 0, m>>>(yb, ag, M);
        evA_prev = ei_ctr; cudaEventRecord(ev[ei_ctr++], m);
        k_gemm<2><<<gridG, 256, 0, m>>>(ag, hin, Wupd[st], nullptr, h1p, M);

        // ---- main: topk pool
        k_scores<<<(M + 3) / 4, 128, 0, m>>>(h1p, wp[st], M);
        k_select<<<BGR, 1024, 0, m>>>(n, kk);
        if (evR_prev >= 0) cudaStreamWaitEvent(m, ev[evR_prev], 0);   // prev remap read newpos
        k_compact<<<(M + 1 + 255) / 256, 256, 0, m>>>(M, n, kk, Mn);
        int evC = ei_ctr; cudaEventRecord(ev[ei_ctr++], m);
        if (evRP_prev >= 0) cudaStreamWaitEvent(m, ev[evRP_prev], 0); // prev rpart read h2p
        k_gather<<<(Mn * 32 + 255) / 256, 256, 0, m>>>(h1p, h2p, Mn);
        int evG = ei_ctr; cudaEventRecord(ev[ei_ctr++], m);

        // ---- side: remap + readout (overlap next-stage gemms)
        if (st < 2) {
            cudaStreamWaitEvent(sd, ev[evC], 0);
            int* eo = (st == 0) ? eA : eB;
            k_remap<<<(EMAX + 255) / 256, 256, 0, sd>>>(es, ed, eo, EMAX, Mn);
            evR_prev = ei_ctr; cudaEventRecord(ev[ei_ctr++], sd);
            es = eo;
            ed = eo + EMAX;
        } else {
            evR_prev = -1;
        }
        cudaStreamWaitEvent(sd, ev[evG], 0);
        k_rpart<<<BGR * CH, 128, 0, sd>>>(h2p, kk);
        k_rfinal<<<BGR, 256, 0, sd>>>(kk, st == 0 ? 1 : 0);
        evRP_prev = ei_ctr; cudaEventRecord(ev[ei_ctr++], sd);

        hin = h2p;
    }

    // join + final MLP
    cudaStreamWaitEvent(m, ev[evRP_prev], 0);
    k_mlp<<<1, 256, 0, m>>>(Wl1, bl1, Wl2, bl2, Wl3, bl3, (float*)d_out);
}

// round 9
// speedup vs baseline: 1.5228x; 1.3265x over previous
#include <cuda_runtime.h>
#include <cuda_fp16.h>
#include <math.h>
#include <stdint.h>
#include <mma.h>

using namespace nvcuda;

#define F 128
#define NMAX 100000
#define EMAX 1600000
#define BGR 8
#define CH 40
#define CAPD 96
#define BKP 48

// ---------------- device scratch ----------------
__device__ float  g_y[NMAX * F];
__device__ float  g_h1[NMAX * F];
__device__ float  g_h2[80000 * F];
__device__ __half g_xh[NMAX * F];      // hi split of current gemm1 input
__device__ __half g_xl[NMAX * F];      // lo split
__device__ __half g_ah[NMAX * F];      // hi split of aggr
__device__ __half g_al[NMAX * F];      // lo split
__device__ __half g_w1h[128 * 128];
__device__ __half g_w1l[128 * 128];
__device__ __half g_w2h[128 * 256];
__device__ __half g_w2l[128 * 256];
__device__ int    g_eA[2 * EMAX];
__device__ int    g_eB[2 * EMAX];
__device__ int    g_deg[NMAX];
__device__ int    g_bkt[NMAX * CAPD];
__device__ float  g_s[NMAX];
__device__ int    g_newpos[NMAX + 1];
__device__ int    g_gidx[80000];
__device__ float  g_tanhv[80000];
__device__ unsigned g_thr[BGR];
__device__ int    g_needeq[BGR];
__device__ int    g_cnt[BGR];
__device__ int    g_eqcnt[BGR];
__device__ float  g_z[BGR * 2 * F];
__device__ float  g_part[BGR * CH * 2 * F];

__device__ __forceinline__ unsigned ordkey(float f) {
    unsigned u = __float_as_uint(f);
    return (u & 0x80000000u) ? ~u : (u | 0x80000000u);
}

__device__ __forceinline__ void split2(float v, __half& h, __half& l) {
    h = __float2half_rn(v);
    l = __float2half_rn(v - __half2float(h));
}

// ---------------- elementwise fp16 hi/lo split ----------------
__global__ void k_split(const float* __restrict__ src, __half* __restrict__ hi,
                        __half* __restrict__ lo, int n4)
{
    int i = blockIdx.x * blockDim.x + threadIdx.x;
    if (i >= n4) return;
    float4 v = ((const float4*)src)[i];
    __half h0, h1, h2, h3, l0, l1, l2, l3;
    split2(v.x, h0, l0); split2(v.y, h1, l1);
    split2(v.z, h2, l2); split2(v.w, h3, l3);
    ((__half2*)hi)[i * 2 + 0] = __halves2half2(h0, h1);
    ((__half2*)hi)[i * 2 + 1] = __halves2half2(h2, h3);
    ((__half2*)lo)[i * 2 + 0] = __halves2half2(l0, l1);
    ((__half2*)lo)[i * 2 + 1] = __halves2half2(l2, l3);
}

// ---------------- fp16-split wmma GEMM: C = relu(A1@W[:, :128]^T (+A2@W[:,128:]^T) + bias)
// A given as hi/lo half arrays; W as hi/lo half arrays [128][K]. 3 MMA products.
template <int KPARTS>
__global__ __launch_bounds__(256)
void k_gemm_h(const __half* __restrict__ Ah1, const __half* __restrict__ Al1,
              const __half* __restrict__ Ah2, const __half* __restrict__ Al2,
              const __half* __restrict__ Wh, const __half* __restrict__ Wl,
              const float* __restrict__ bias, float* __restrict__ C, int M)
{
    extern __shared__ char dsm[];
    __half (*sAh)[BKP] = (__half(*)[BKP])(dsm);
    __half (*sAl)[BKP] = (__half(*)[BKP])(dsm + 12288);
    __half (*sWh)[BKP] = (__half(*)[BKP])(dsm + 24576);
    __half (*sWl)[BKP] = (__half(*)[BKP])(dsm + 36864);
    float (*stage)[256] = (float(*)[256])(dsm + 49152);

    const int tid = threadIdx.x, wid = tid >> 5, lane = tid & 31;
    const int warp_m = wid & 1;          // 64 rows each
    const int warp_n = wid >> 1;         // 32 cols each
    const int r0 = blockIdx.x * 128;
    const int K = KPARTS * 128;
    const int NCH = KPARTS * 4;
    const int lrow = tid >> 1, lcol = (tid & 1) * 16;

    wmma::fragment<wmma::accumulator, 16, 16, 16, float> acc[4][2];
#pragma unroll
    for (int i = 0; i < 4; i++)
#pragma unroll
        for (int j = 0; j < 2; j++) wmma::fill_fragment(acc[i][j], 0.f);

    for (int c = 0; c < NCH; ++c) {
        const __half* Ah = Ah1; const __half* Al = Al1;
        int acol = c * 32;
        if (KPARTS == 2 && c >= 4) { Ah = Ah2; Al = Al2; acol = (c - 4) * 32; }

        int gr = r0 + lrow;
        if (gr < M) {
            *(uint4*)&sAh[lrow][lcol]     = *(const uint4*)(Ah + (size_t)gr * F + acol + lcol);
            *(uint4*)&sAh[lrow][lcol + 8] = *(const uint4*)(Ah + (size_t)gr * F + acol + lcol + 8);
            *(uint4*)&sAl[lrow][lcol]     = *(const uint4*)(Al + (size_t)gr * F + acol + lcol);
            *(uint4*)&sAl[lrow][lcol + 8] = *(const uint4*)(Al + (size_t)gr * F + acol + lcol + 8);
        } else {
            uint4 z = make_uint4(0, 0, 0, 0);
            *(uint4*)&sAh[lrow][lcol] = z; *(uint4*)&sAh[lrow][lcol + 8] = z;
            *(uint4*)&sAl[lrow][lcol] = z; *(uint4*)&sAl[lrow][lcol + 8] = z;
        }
        *(uint4*)&sWh[lrow][lcol]     = *(const uint4*)(Wh + (size_t)lrow * K + c * 32 + lcol);
        *(uint4*)&sWh[lrow][lcol + 8] = *(const uint4*)(Wh + (size_t)lrow * K + c * 32 + lcol + 8);
        *(uint4*)&sWl[lrow][lcol]     = *(const uint4*)(Wl + (size_t)lrow * K + c * 32 + lcol);
        *(uint4*)&sWl[lrow][lcol + 8] = *(const uint4*)(Wl + (size_t)lrow * K + c * 32 + lcol + 8);
        __syncthreads();

#pragma unroll
        for (int ks = 0; ks < 2; ks++) {
            wmma::fragment<wmma::matrix_b, 16, 16, 16, __half, wmma::col_major> bh[2], bl[2];
#pragma unroll
            for (int wn = 0; wn < 2; wn++) {
                wmma::load_matrix_sync(bh[wn], &sWh[warp_n * 32 + wn * 16][ks * 16], BKP);
                wmma::load_matrix_sync(bl[wn], &sWl[warp_n * 32 + wn * 16][ks * 16], BKP);
            }
#pragma unroll
            for (int wm = 0; wm < 4; wm++) {
                wmma::fragment<wmma::matrix_a, 16, 16, 16, __half, wmma::row_major> ah, al;
                wmma::load_matrix_sync(ah, &sAh[warp_m * 64 + wm * 16][ks * 16], BKP);
                wmma::load_matrix_sync(al, &sAl[warp_m * 64 + wm * 16][ks * 16], BKP);
#pragma unroll
                for (int wn = 0; wn < 2; wn++) {
                    wmma::mma_sync(acc[wm][wn], ah, bh[wn], acc[wm][wn]);
                    wmma::mma_sync(acc[wm][wn], ah, bl[wn], acc[wm][wn]);
                    wmma::mma_sync(acc[wm][wn], al, bh[wn], acc[wm][wn]);
                }
            }
        }
        __syncthreads();
    }

    // epilogue: stage each 16x16 frag, bias+relu, coalesced write
#pragma unroll
    for (int wm = 0; wm < 4; wm++)
#pragma unroll
        for (int wn = 0; wn < 2; wn++) {
            wmma::store_matrix_sync(stage[wid], acc[wm][wn], 16, wmma::mem_row_major);
            __syncwarp();
            int m0 = warp_m * 64 + wm * 16;
            int n0 = warp_n * 32 + wn * 16;
#pragma unroll
            for (int e = 0; e < 8; e++) {
                int idx = e * 32 + lane;
                int row = idx >> 4, col = idx & 15;
                int gr = r0 + m0 + row;
                if (gr < M) {
                    int gc = n0 + col;
                    float v = stage[wid][idx] + (bias ? bias[gc] : 0.f);
                    C[(size_t)gr * F + gc] = fmaxf(v, 0.f);
                }
            }
            __syncwarp();
        }
}

// ---------------- CSR-bucket build ----------------
__global__ void k_zerodeg(int M)
{
    int i = blockIdx.x * blockDim.x + threadIdx.x;
    if (i < M) g_deg[i] = 0;
}

__global__ void k_bucket(const int* __restrict__ esrc, const int* __restrict__ edst,
                         int E, int M)
{
    int t = blockIdx.x * blockDim.x + threadIdx.x;
    int half = E >> 1;
    if (t >= half) return;
#pragma unroll
    for (int q = 0; q < 2; q++) {
        int e = t + q * half;
        int d = edst[e];
        if (d >= M) continue;
        int s = esrc[e];
        int pos = atomicAdd(&g_deg[d], 1);
        if (pos < CAPD) g_bkt[(size_t)d * CAPD + pos] = s;
    }
}

// ---------------- gather-max: warp per dst node; writes hi/lo fp16 splits ----------------
__global__ void k_aggr(const float* __restrict__ y, int M)
{
    int warp = blockIdx.x * (blockDim.x >> 5) + (threadIdx.x >> 5);
    int lane = threadIdx.x & 31;
    if (warp >= M) return;
    int dv = g_deg[warp];
    if (dv > CAPD) dv = CAPD;
    const int* b = g_bkt + (size_t)warp * CAPD;
    float4 acc = ((const float4*)(y + (size_t)warp * F))[lane];
    int i = 0;
    for (; i + 1 < dv; i += 2) {
        int s0 = b[i], s1 = b[i + 1];
        float4 t0 = ((const float4*)(y + (size_t)s0 * F))[lane];
        float4 t1 = ((const float4*)(y + (size_t)s1 * F))[lane];
        acc.x = fmaxf(acc.x, fmaxf(t0.x, t1.x));
        acc.y = fmaxf(acc.y, fmaxf(t0.y, t1.y));
        acc.z = fmaxf(acc.z, fmaxf(t0.z, t1.z));
        acc.w = fmaxf(acc.w, fmaxf(t0.w, t1.w));
    }
    if (i < dv) {
        int s0 = b[i];
        float4 t0 = ((const float4*)(y + (size_t)s0 * F))[lane];
        acc.x = fmaxf(acc.x, t0.x);
        acc.y = fmaxf(acc.y, t0.y);
        acc.z = fmaxf(acc.z, t0.z);
        acc.w = fmaxf(acc.w, t0.w);
    }
    __half h0, h1, h2, h3, l0, l1, l2, l3;
    split2(acc.x, h0, l0); split2(acc.y, h1, l1);
    split2(acc.z, h2, l2); split2(acc.w, h3, l3);
    __half2* oh = (__half2*)(g_ah + (size_t)warp * F + lane * 4);
    __half2* ol = (__half2*)(g_al + (size_t)warp * F + lane * 4);
    oh[0] = __halves2half2(h0, h1); oh[1] = __halves2half2(h2, h3);
    ol[0] = __halves2half2(l0, l1); ol[1] = __halves2half2(l2, l3);
}

// ---------------- scores (wnorm fused) ----------------
__global__ void k_scores(const float* __restrict__ h, const float* __restrict__ w, int M)
{
    __shared__ float s_inv;
    int lane = threadIdx.x & 31;
    if (threadIdx.x < 32) {
        float4 b0 = ((const float4*)w)[lane];
        float sq = b0.x * b0.x + b0.y * b0.y + b0.z * b0.z + b0.w * b0.w;
        for (int o = 16; o > 0; o >>= 1) sq += __shfl_down_sync(0xffffffffu, sq, o);
        if (lane == 0) s_inv = rsqrtf(sq);
    }
    __syncthreads();
    int warp = blockIdx.x * (blockDim.x >> 5) + (threadIdx.x >> 5);
    if (warp >= M) return;
    float4 a = ((const float4*)(h + (size_t)warp * F))[lane];
    float4 b = ((const float4*)w)[lane];
    float d = a.x * b.x + a.y * b.y + a.z * b.z + a.w * b.w;
    for (int o = 16; o > 0; o >>= 1) d += __shfl_down_sync(0xffffffffu, d, o);
    if (lane == 0) g_s[warp] = d * s_inv;
}

// ---------------- per-graph exact radix select (also zeroes pool counters) ----------------
__global__ __launch_bounds__(1024)
void k_select(int n, int kk)
{
    int g = blockIdx.x;
    const float* sg = g_s + (size_t)g * n;
    __shared__ unsigned hist[256];
    __shared__ unsigned s_prefix, s_mask;
    __shared__ int s_need;
    if (threadIdx.x == 0) { s_prefix = 0; s_mask = 0; s_need = kk; }
    __syncthreads();
    for (int pass = 0; pass < 4; ++pass) {
        int shift = 24 - 8 * pass;
        if (threadIdx.x < 256) hist[threadIdx.x] = 0;
        __syncthreads();
        unsigned pre = s_prefix, msk = s_mask;
        for (int i = threadIdx.x; i < n; i += blockDim.x) {
            unsigned key = ordkey(sg[i]);
            if ((key & msk) == pre) atomicAdd(&hist[(key >> shift) & 255], 1u);
        }
        __syncthreads();
        if (threadIdx.x == 0) {
            int need = s_need;
            unsigned cum = 0;
            for (int b = 255; b >= 0; --b) {
                unsigned h = hist[b];
                if (cum + h >= (unsigned)need) {
                    s_need = need - (int)cum;
                    s_prefix = pre | ((unsigned)b << shift);
                    s_mask = msk | (255u << shift);
                    break;
                }
                cum += h;
            }
        }
        __syncthreads();
    }
    if (threadIdx.x == 0) {
        g_thr[g] = s_prefix; g_needeq[g] = s_need;
        g_cnt[g] = 0; g_eqcnt[g] = 0;
    }
}

// ---------------- compact (initpool fused) ----------------
__global__ void k_compact(int M, int n, int kk, int Mn)
{
    int v = blockIdx.x * blockDim.x + threadIdx.x;
    if (v > M) return;
    if (v == M) { g_newpos[M] = Mn; return; }
    int g = v / n;
    float sv = g_s[v];
    unsigned key = ordkey(sv);
    unsigned T = g_thr[g];
    bool keep = false;
    if (key > T) keep = true;
    else if (key == T && atomicAdd(&g_eqcnt[g], 1) < g_needeq[g]) keep = true;
    if (!keep) { g_newpos[v] = Mn; return; }
    int pos = atomicAdd(&g_cnt[g], 1);
    int j = g * kk + pos;
    g_newpos[v] = j;
    g_gidx[j] = v;
    g_tanhv[j] = tanhf(sv);
}

// ---------------- gather: float out + fp16 splits for next gemm1 ----------------
__global__ void k_gather(const float* __restrict__ h, float* __restrict__ xnew, int Mn)
{
    int idx = blockIdx.x * blockDim.x + threadIdx.x;
    int j = idx >> 5, q = idx & 31;
    if (j >= Mn) return;
    float t = g_tanhv[j];
    float4 v = *(const float4*)(h + (size_t)g_gidx[j] * F + q * 4);
    v.x *= t; v.y *= t; v.z *= t; v.w *= t;
    *(float4*)(xnew + (size_t)j * F + q * 4) = v;
    __half h0, h1, h2, h3, l0, l1, l2, l3;
    split2(v.x, h0, l0); split2(v.y, h1, l1);
    split2(v.z, h2, l2); split2(v.w, h3, l3);
    __half2* oh = (__half2*)(g_xh + (size_t)j * F + q * 4);
    __half2* ol = (__half2*)(g_xl + (size_t)j * F + q * 4);
    oh[0] = __halves2half2(h0, h1); oh[1] = __halves2half2(h2, h3);
    ol[0] = __halves2half2(l0, l1); ol[1] = __halves2half2(l2, l3);
}

__global__ void k_remap(const int* __restrict__ es, const int* __restrict__ ed,
                        int* __restrict__ eo, int E, int Mn)
{
    int i = blockIdx.x * blockDim.x + threadIdx.x;
    if (i >= E) return;
    int s = g_newpos[es[i]];
    int d = g_newpos[ed[i]];
    if (s == Mn || d == Mn) { s = Mn; d = Mn; }
    eo[i] = s;
    eo[E + i] = d;
}

// ---------------- readout ----------------
__global__ void k_rpart(const float* __restrict__ x, int kk)
{
    int g = blockIdx.x / CH, c = blockIdx.x % CH;
    int rpc = kk / CH;
    int f = threadIdx.x;  // 128
    const float* base = x + ((size_t)g * kk + (size_t)c * rpc) * F + f;
    float vmax = -3.4e38f, vsum = 0.f;
    for (int r = 0; r < rpc; r++) {
        float v = base[(size_t)r * F];
        vmax = fmaxf(vmax, v);
        vsum += v;
    }
    float* p = g_part + (size_t)blockIdx.x * 2 * F;
    p[f] = vmax;
    p[F + f] = vsum;
}

__global__ void k_rfinal(int kk, int store)
{
    int g = blockIdx.x;
    int f = threadIdx.x;  // 256
    const float* p = g_part + (size_t)g * CH * 2 * F;
    float r;
    if (f < F) {
        float m = -3.4e38f;
        for (int c = 0; c < CH; c++) m = fmaxf(m, p[c * 2 * F + f]);
        r = m;
    } else {
        float s = 0.f;
        for (int c = 0; c < CH; c++) s += p[c * 2 * F + f];
        r = s / (float)kk;
    }
    if (store) g_z[g * 2 * F + f] = r;
    else       g_z[g * 2 * F + f] += r;
}

// ---------------- final MLP + sigmoid ----------------
__global__ void k_mlp(const float* __restrict__ Wl1, const float* __restrict__ bl1,
                      const float* __restrict__ Wl2, const float* __restrict__ bl2,
                      const float* __restrict__ Wl3, const float* __restrict__ bl3,
                      float* __restrict__ out)
{
    __shared__ float sz[BGR][2 * F];
    __shared__ float h1[BGR][F];
    __shared__ float h2[BGR][64];
    int t = threadIdx.x;  // 256
    for (int i = t; i < BGR * 2 * F; i += 256) ((float*)sz)[i] = g_z[i];
    __syncthreads();
    for (int o = t; o < BGR * F; o += 256) {
        int g = o >> 7, r = o & 127;
        float a = bl1[r];
        const float* wr = Wl1 + (size_t)r * 2 * F;
        for (int c = 0; c < 2 * F; c++) a += sz[g][c] * wr[c];
        h1[g][r] = fmaxf(a, 0.f);
    }
    __syncthreads();
    for (int o = t; o < BGR * 64; o += 256) {
        int g = o >> 6, r = o & 63;
        float a = bl2[r];
        const float* wr = Wl2 + (size_t)r * F;
        for (int c = 0; c < F; c++) a += h1[g][c] * wr[c];
        h2[g][r] = fmaxf(a, 0.f);
    }
    __syncthreads();
    if (t < BGR) {
        float a = bl3[0];
        for (int c = 0; c < 64; c++) a += h2[t][c] * Wl3[c];
        out[t] = 1.f / (1.f + expf(-a));
    }
}

// ---------------- orchestration (serial stream) ----------------
#define SMEM_H (57344)

extern "C" void kernel_launch(void* const* d_in, const int* in_sizes, int n_in,
                              void* d_out, int out_size)
{
    const float* x = (const float*)d_in[0];
    const int* ei = (const int*)d_in[1];
    const float* Wlin[3] = { (const float*)d_in[2], (const float*)d_in[6], (const float*)d_in[10] };
    const float* blin[3] = { (const float*)d_in[3], (const float*)d_in[7], (const float*)d_in[11] };
    const float* Wupd[3] = { (const float*)d_in[4], (const float*)d_in[8], (const float*)d_in[12] };
    const float* wp[3]   = { (const float*)d_in[5], (const float*)d_in[9], (const float*)d_in[13] };
    const float* Wl1 = (const float*)d_in[14];
    const float* bl1 = (const float*)d_in[15];
    const float* Wl2 = (const float*)d_in[16];
    const float* bl2 = (const float*)d_in[17];
    const float* Wl3 = (const float*)d_in[18];
    const float* bl3 = (const float*)d_in[19];

    float *yb, *h1p, *h2p;
    __half *xh, *xl, *ah, *al, *w1h, *w1l, *w2h, *w2l;
    int *eA, *eB;
    cudaGetSymbolAddress((void**)&yb, g_y);
    cudaGetSymbolAddress((void**)&h1p, g_h1);
    cudaGetSymbolAddress((void**)&h2p, g_h2);
    cudaGetSymbolAddress((void**)&xh, g_xh);
    cudaGetSymbolAddress((void**)&xl, g_xl);
    cudaGetSymbolAddress((void**)&ah, g_ah);
    cudaGetSymbolAddress((void**)&al, g_al);
    cudaGetSymbolAddress((void**)&w1h, g_w1h);
    cudaGetSymbolAddress((void**)&w1l, g_w1l);
    cudaGetSymbolAddress((void**)&w2h, g_w2h);
    cudaGetSymbolAddress((void**)&w2l, g_w2l);
    cudaGetSymbolAddress((void**)&eA, g_eA);
    cudaGetSymbolAddress((void**)&eB, g_eB);

    static int init_done = 0;
    if (!init_done) {
        cudaFuncSetAttribute(k_gemm_h<1>, cudaFuncAttributeMaxDynamicSharedMemorySize, SMEM_H);
        cudaFuncSetAttribute(k_gemm_h<2>, cudaFuncAttributeMaxDynamicSharedMemorySize, SMEM_H);
        init_done = 1;
    }

    const int Ms[3] = { 100000, 80000, 64000 };
    const int kks[3] = { 10000, 8000, 6400 };

    const int* es = ei;
    const int* ed = ei + EMAX;

    // stage-1 input split
    k_split<<<(NMAX * F / 4 + 255) / 256, 256>>>(x, xh, xl, NMAX * F / 4);

    for (int st = 0; st < 3; ++st) {
        int M = Ms[st];
        int gridG = (M + 127) / 128;
        int kk = kks[st], n = M / BGR, Mn = BGR * kk;

        // weight splits (tiny)
        k_split<<<(128 * 128 / 4 + 255) / 256, 256>>>(Wlin[st], w1h, w1l, 128 * 128 / 4);
        k_split<<<(128 * 256 / 4 + 255) / 256, 256>>>(Wupd[st], w2h, w2l, 128 * 256 / 4);

        // SAGEConv
        k_gemm_h<1><<<gridG, 256, SMEM_H>>>(xh, xl, nullptr, nullptr, w1h, w1l, blin[st], yb, M);
        k_zerodeg<<<(M + 255) / 256, 256>>>(M);
        k_bucket<<<(EMAX / 2 + 255) / 256, 256>>>(es, ed, EMAX, M);
        k_aggr<<<(M + 7) / 8, 256>>>(yb, M);
        k_gemm_h<2><<<gridG, 256, SMEM_H>>>(ah, al, xh, xl, w2h, w2l, nullptr, h1p, M);

        // TopK pool
        k_scores<<<(M + 3) / 4, 128>>>(h1p, wp[st], M);
        k_select<<<BGR, 1024>>>(n, kk);
        k_compact<<<(M + 1 + 255) / 256, 256>>>(M, n, kk, Mn);
        k_gather<<<(Mn * 32 + 255) / 256, 256>>>(h1p, h2p, Mn);
        if (st < 2) {
            int* eo = (st == 0) ? eA : eB;
            k_remap<<<(EMAX + 255) / 256, 256>>>(es, ed, eo, EMAX, Mn);
            es = eo;
            ed = eo + EMAX;
        }

        // readout
        k_rpart<<<BGR * CH, 128>>>(h2p, kk);
        k_rfinal<<<BGR, 256>>>(kk, st == 0 ? 1 : 0);
    }

    k_mlp<<<1, 256>>>(Wl1, bl1, Wl2, bl2, Wl3, bl3, (float*)d_out);
}

// round 10
// speedup vs baseline: 1.6890x; 1.1091x over previous
#include <cuda_runtime.h>
#include <cuda_fp16.h>
#include <math.h>
#include <stdint.h>
#include <mma.h>

using namespace nvcuda;

#define F 128
#define NMAX 100000
#define EMAX 1600000
#define BGR 8
#define CH 40
#define CAPD 96
#define BKP 48

// ---------------- device scratch ----------------
__device__ float  g_y[NMAX * F];
__device__ float  g_h1[NMAX * F];
__device__ float  g_h2[80000 * F];
__device__ __half g_xh[NMAX * F];
__device__ __half g_xl[NMAX * F];
__device__ __half g_ah[NMAX * F];
__device__ __half g_al[NMAX * F];
__device__ __half g_w1h[128 * 128];
__device__ __half g_w1l[128 * 128];
__device__ __half g_w2h[128 * 256];
__device__ __half g_w2l[128 * 256];
__device__ int    g_eA[2 * EMAX];
__device__ int    g_eB[2 * EMAX];
__device__ int    g_deg[NMAX];
__device__ int    g_bkt[NMAX * CAPD];
__device__ float  g_s[NMAX];
__device__ int    g_newpos[NMAX + 1];
__device__ int    g_gidx[80000];
__device__ float  g_tanhv[80000];
__device__ unsigned g_thr[BGR];
__device__ int    g_needeq[BGR];
__device__ int    g_cnt[BGR];
__device__ int    g_eqcnt[BGR];
__device__ float  g_z[BGR * 2 * F];
__device__ float  g_part[BGR * CH * 2 * F];

__device__ __forceinline__ unsigned ordkey(float f) {
    unsigned u = __float_as_uint(f);
    return (u & 0x80000000u) ? ~u : (u | 0x80000000u);
}

__device__ __forceinline__ void split2(float v, __half& h, __half& l) {
    h = __float2half_rn(v);
    l = __float2half_rn(v - __half2float(h));
}

__device__ __forceinline__ void cp16(uint32_t saddr, const void* gptr, bool valid) {
    int sz = valid ? 16 : 0;
    asm volatile("cp.async.cg.shared.global [%0], [%1], 16, %2;"
                 :: "r"(saddr), "l"(gptr), "r"(sz));
}
#define CP_COMMIT() asm volatile("cp.async.commit_group;" ::: "memory")
#define CP_WAIT1()  asm volatile("cp.async.wait_group 1;" ::: "memory")
#define CP_WAIT0()  asm volatile("cp.async.wait_group 0;" ::: "memory")

// ---------------- elementwise fp16 hi/lo split ----------------
__global__ void k_split(const float* __restrict__ src, __half* __restrict__ hi,
                        __half* __restrict__ lo, int n4)
{
    int i = blockIdx.x * blockDim.x + threadIdx.x;
    if (i >= n4) return;
    float4 v = ((const float4*)src)[i];
    __half h0, h1, h2, h3, l0, l1, l2, l3;
    split2(v.x, h0, l0); split2(v.y, h1, l1);
    split2(v.z, h2, l2); split2(v.w, h3, l3);
    ((__half2*)hi)[i * 2 + 0] = __halves2half2(h0, h1);
    ((__half2*)hi)[i * 2 + 1] = __halves2half2(h2, h3);
    ((__half2*)lo)[i * 2 + 0] = __halves2half2(l0, l1);
    ((__half2*)lo)[i * 2 + 1] = __halves2half2(l2, l3);
}

// dual weight split: W1 (128x128) and W2 (128x256) in one launch
__global__ void k_splitw(const float* __restrict__ W1, const float* __restrict__ W2)
{
    int i = blockIdx.x * blockDim.x + threadIdx.x;
    const int n1 = 128 * 128 / 4;
    const int n2 = 128 * 256 / 4;
    const float* src; __half *hi, *lo; int idx;
    if (i < n1) { src = W1; idx = i;
        float4 v = ((const float4*)src)[idx];
        __half h0, h1, h2, h3, l0, l1, l2, l3;
        split2(v.x, h0, l0); split2(v.y, h1, l1);
        split2(v.z, h2, l2); split2(v.w, h3, l3);
        ((__half2*)g_w1h)[idx * 2 + 0] = __halves2half2(h0, h1);
        ((__half2*)g_w1h)[idx * 2 + 1] = __halves2half2(h2, h3);
        ((__half2*)g_w1l)[idx * 2 + 0] = __halves2half2(l0, l1);
        ((__half2*)g_w1l)[idx * 2 + 1] = __halves2half2(l2, l3);
    } else if (i < n1 + n2) { idx = i - n1;
        float4 v = ((const float4*)W2)[idx];
        __half h0, h1, h2, h3, l0, l1, l2, l3;
        split2(v.x, h0, l0); split2(v.y, h1, l1);
        split2(v.z, h2, l2); split2(v.w, h3, l3);
        ((__half2*)g_w2h)[idx * 2 + 0] = __halves2half2(h0, h1);
        ((__half2*)g_w2h)[idx * 2 + 1] = __halves2half2(h2, h3);
        ((__half2*)g_w2l)[idx * 2 + 0] = __halves2half2(l0, l1);
        ((__half2*)g_w2l)[idx * 2 + 1] = __halves2half2(l2, l3);
    }
}

// ---------------- fp16-split wmma GEMM with cp.async double buffering ----------------
// C = relu(A1@W[:, :128]^T (+A2@W[:,128:]^T) + bias); 3 MMA products.
#define STG_B 12288                    // one 128x32 half tile with BKP=48 stride
#define STAGE_B (4 * STG_B)            // Ah, Al, Wh, Wl
#define SMEM_H (2 * STAGE_B + 8192)    // 2 stages + fp32 epilogue stage

template <int KPARTS>
__global__ __launch_bounds__(256)
void k_gemm_h(const __half* __restrict__ Ah1, const __half* __restrict__ Al1,
              const __half* __restrict__ Ah2, const __half* __restrict__ Al2,
              const __half* __restrict__ Wh, const __half* __restrict__ Wl,
              const float* __restrict__ bias, float* __restrict__ C, int M)
{
    extern __shared__ __align__(16) char dsm[];
    float (*stage)[256] = (float(*)[256])(dsm + 2 * STAGE_B);
    uint32_t sbase;
    asm("{ .reg .u64 t; cvta.to.shared.u64 t, %1; cvt.u32.u64 %0, t; }"
        : "=r"(sbase) : "l"(dsm));

    const int tid = threadIdx.x, wid = tid >> 5, lane = tid & 31;
    const int warp_m = wid & 1;
    const int warp_n = wid >> 1;
    const int r0 = blockIdx.x * 128;
    const int K = KPARTS * 128;
    const int NCH = KPARTS * 4;

    // each thread issues 2 chunks per array; chunk q: row=q>>2, 16B piece (q&3)
    const int q0 = tid, q1 = tid + 256;
    const int row0 = q0 >> 2, p0 = q0 & 3;
    const int row1 = q1 >> 2, p1 = q1 & 3;

    auto issue = [&](int c) {
        const __half* Ah = Ah1; const __half* Al = Al1;
        int acol = c * 32;
        if (KPARTS == 2 && c >= 4) { Ah = Ah2; Al = Al2; acol = (c - 4) * 32; }
        uint32_t st = sbase + (c & 1) * STAGE_B;
        int gr0 = r0 + row0, gr1 = r0 + row1;
        // A hi / lo
        cp16(st + row0 * 96 + p0 * 16, Ah + (size_t)gr0 * F + acol + p0 * 8, gr0 < M);
        cp16(st + row1 * 96 + p1 * 16, Ah + (size_t)gr1 * F + acol + p1 * 8, gr1 < M);
        cp16(st + STG_B + row0 * 96 + p0 * 16, Al + (size_t)gr0 * F + acol + p0 * 8, gr0 < M);
        cp16(st + STG_B + row1 * 96 + p1 * 16, Al + (size_t)gr1 * F + acol + p1 * 8, gr1 < M);
        // W hi / lo
        cp16(st + 2 * STG_B + row0 * 96 + p0 * 16, Wh + (size_t)row0 * K + c * 32 + p0 * 8, true);
        cp16(st + 2 * STG_B + row1 * 96 + p1 * 16, Wh + (size_t)row1 * K + c * 32 + p1 * 8, true);
        cp16(st + 3 * STG_B + row0 * 96 + p0 * 16, Wl + (size_t)row0 * K + c * 32 + p0 * 8, true);
        cp16(st + 3 * STG_B + row1 * 96 + p1 * 16, Wl + (size_t)row1 * K + c * 32 + p1 * 8, true);
        CP_COMMIT();
    };

    wmma::fragment<wmma::accumulator, 16, 16, 16, float> acc[4][2];
#pragma unroll
    for (int i = 0; i < 4; i++)
#pragma unroll
        for (int j = 0; j < 2; j++) wmma::fill_fragment(acc[i][j], 0.f);

    issue(0);

    for (int c = 0; c < NCH; ++c) {
        if (c + 1 < NCH) issue(c + 1);
        if (c + 1 < NCH) CP_WAIT1(); else CP_WAIT0();
        __syncthreads();

        const char* st = dsm + (c & 1) * STAGE_B;
        const __half (*sAh)[BKP] = (const __half(*)[BKP])(st);
        const __half (*sAl)[BKP] = (const __half(*)[BKP])(st + STG_B);
        const __half (*sWh)[BKP] = (const __half(*)[BKP])(st + 2 * STG_B);
        const __half (*sWl)[BKP] = (const __half(*)[BKP])(st + 3 * STG_B);

#pragma unroll
        for (int ks = 0; ks < 2; ks++) {
            wmma::fragment<wmma::matrix_b, 16, 16, 16, __half, wmma::col_major> bh[2], bl[2];
#pragma unroll
            for (int wn = 0; wn < 2; wn++) {
                wmma::load_matrix_sync(bh[wn], &sWh[warp_n * 32 + wn * 16][ks * 16], BKP);
                wmma::load_matrix_sync(bl[wn], &sWl[warp_n * 32 + wn * 16][ks * 16], BKP);
            }
#pragma unroll
            for (int wm = 0; wm < 4; wm++) {
                wmma::fragment<wmma::matrix_a, 16, 16, 16, __half, wmma::row_major> ah, al;
                wmma::load_matrix_sync(ah, &sAh[warp_m * 64 + wm * 16][ks * 16], BKP);
                wmma::load_matrix_sync(al, &sAl[warp_m * 64 + wm * 16][ks * 16], BKP);
#pragma unroll
                for (int wn = 0; wn < 2; wn++) {
                    wmma::mma_sync(acc[wm][wn], ah, bh[wn], acc[wm][wn]);
                    wmma::mma_sync(acc[wm][wn], ah, bl[wn], acc[wm][wn]);
                    wmma::mma_sync(acc[wm][wn], al, bh[wn], acc[wm][wn]);
                }
            }
        }
        __syncthreads();
    }

    // epilogue
#pragma unroll
    for (int wm = 0; wm < 4; wm++)
#pragma unroll
        for (int wn = 0; wn < 2; wn++) {
            wmma::store_matrix_sync(stage[wid], acc[wm][wn], 16, wmma::mem_row_major);
            __syncwarp();
            int m0 = warp_m * 64 + wm * 16;
            int n0 = warp_n * 32 + wn * 16;
#pragma unroll
            for (int e = 0; e < 8; e++) {
                int idx = e * 32 + lane;
                int row = idx >> 4, col = idx & 15;
                int gr = r0 + m0 + row;
                if (gr < M) {
                    int gc = n0 + col;
                    float v = stage[wid][idx] + (bias ? bias[gc] : 0.f);
                    C[(size_t)gr * F + gc] = fmaxf(v, 0.f);
                }
            }
            __syncwarp();
        }
}

// ---------------- CSR-bucket build ----------------
__global__ void k_zerodeg(int M)
{
    int i = blockIdx.x * blockDim.x + threadIdx.x;
    if (i < M) g_deg[i] = 0;
}

__global__ void k_bucket(const int* __restrict__ esrc, const int* __restrict__ edst,
                         int E, int M)
{
    int t = blockIdx.x * blockDim.x + threadIdx.x;
    int half = E >> 1;
    if (t >= half) return;
#pragma unroll
    for (int q = 0; q < 2; q++) {
        int e = t + q * half;
        int d = edst[e];
        if (d >= M) continue;
        int s = esrc[e];
        int pos = atomicAdd(&g_deg[d], 1);
        if (pos < CAPD) g_bkt[(size_t)d * CAPD + pos] = s;
    }
}

// ---------------- gather-max: warp per dst node; writes hi/lo fp16 splits ----------------
__global__ void k_aggr(const float* __restrict__ y, int M)
{
    int warp = blockIdx.x * (blockDim.x >> 5) + (threadIdx.x >> 5);
    int lane = threadIdx.x & 31;
    if (warp >= M) return;
    int dv = g_deg[warp];
    if (dv > CAPD) dv = CAPD;
    const int* b = g_bkt + (size_t)warp * CAPD;
    float4 acc = ((const float4*)(y + (size_t)warp * F))[lane];
    int i = 0;
    for (; i + 1 < dv; i += 2) {
        int s0 = b[i], s1 = b[i + 1];
        float4 t0 = ((const float4*)(y + (size_t)s0 * F))[lane];
        float4 t1 = ((const float4*)(y + (size_t)s1 * F))[lane];
        acc.x = fmaxf(acc.x, fmaxf(t0.x, t1.x));
        acc.y = fmaxf(acc.y, fmaxf(t0.y, t1.y));
        acc.z = fmaxf(acc.z, fmaxf(t0.z, t1.z));
        acc.w = fmaxf(acc.w, fmaxf(t0.w, t1.w));
    }
    if (i < dv) {
        int s0 = b[i];
        float4 t0 = ((const float4*)(y + (size_t)s0 * F))[lane];
        acc.x = fmaxf(acc.x, t0.x);
        acc.y = fmaxf(acc.y, t0.y);
        acc.z = fmaxf(acc.z, t0.z);
        acc.w = fmaxf(acc.w, t0.w);
    }
    __half h0, h1, h2, h3, l0, l1, l2, l3;
    split2(acc.x, h0, l0); split2(acc.y, h1, l1);
    split2(acc.z, h2, l2); split2(acc.w, h3, l3);
    __half2* oh = (__half2*)(g_ah + (size_t)warp * F + lane * 4);
    __half2* ol = (__half2*)(g_al + (size_t)warp * F + lane * 4);
    oh[0] = __halves2half2(h0, h1); oh[1] = __halves2half2(h2, h3);
    ol[0] = __halves2half2(l0, l1); ol[1] = __halves2half2(l2, l3);
}

// ---------------- scores (wnorm fused) ----------------
__global__ void k_scores(const float* __restrict__ h, const float* __restrict__ w, int M)
{
    __shared__ float s_inv;
    int lane = threadIdx.x & 31;
    if (threadIdx.x < 32) {
        float4 b0 = ((const float4*)w)[lane];
        float sq = b0.x * b0.x + b0.y * b0.y + b0.z * b0.z + b0.w * b0.w;
        for (int o = 16; o > 0; o >>= 1) sq += __shfl_down_sync(0xffffffffu, sq, o);
        if (lane == 0) s_inv = rsqrtf(sq);
    }
    __syncthreads();
    int warp = blockIdx.x * (blockDim.x >> 5) + (threadIdx.x >> 5);
    if (warp >= M) return;
    float4 a = ((const float4*)(h + (size_t)warp * F))[lane];
    float4 b = ((const float4*)w)[lane];
    float d = a.x * b.x + a.y * b.y + a.z * b.z + a.w * b.w;
    for (int o = 16; o > 0; o >>= 1) d += __shfl_down_sync(0xffffffffu, d, o);
    if (lane == 0) g_s[warp] = d * s_inv;
}

// ---------------- per-graph exact radix select (also zeroes pool counters) ----------------
__global__ __launch_bounds__(1024)
void k_select(int n, int kk)
{
    int g = blockIdx.x;
    const float* sg = g_s + (size_t)g * n;
    __shared__ unsigned hist[256];
    __shared__ unsigned s_prefix, s_mask;
    __shared__ int s_need;
    if (threadIdx.x == 0) { s_prefix = 0; s_mask = 0; s_need = kk; }
    __syncthreads();
    for (int pass = 0; pass < 4; ++pass) {
        int shift = 24 - 8 * pass;
        if (threadIdx.x < 256) hist[threadIdx.x] = 0;
        __syncthreads();
        unsigned pre = s_prefix, msk = s_mask;
        for (int i = threadIdx.x; i < n; i += blockDim.x) {
            unsigned key = ordkey(sg[i]);
            if ((key & msk) == pre) atomicAdd(&hist[(key >> shift) & 255], 1u);
        }
        __syncthreads();
        if (threadIdx.x == 0) {
            int need = s_need;
            unsigned cum = 0;
            for (int b = 255; b >= 0; --b) {
                unsigned h = hist[b];
                if (cum + h >= (unsigned)need) {
                    s_need = need - (int)cum;
                    s_prefix = pre | ((unsigned)b << shift);
                    s_mask = msk | (255u << shift);
                    break;
                }
                cum += h;
            }
        }
        __syncthreads();
    }
    if (threadIdx.x == 0) {
        g_thr[g] = s_prefix; g_needeq[g] = s_need;
        g_cnt[g] = 0; g_eqcnt[g] = 0;
    }
}

// ---------------- compact (initpool fused) ----------------
__global__ void k_compact(int M, int n, int kk, int Mn)
{
    int v = blockIdx.x * blockDim.x + threadIdx.x;
    if (v > M) return;
    if (v == M) { g_newpos[M] = Mn; return; }
    int g = v / n;
    float sv = g_s[v];
    unsigned key = ordkey(sv);
    unsigned T = g_thr[g];
    bool keep = false;
    if (key > T) keep = true;
    else if (key == T && atomicAdd(&g_eqcnt[g], 1) < g_needeq[g]) keep = true;
    if (!keep) { g_newpos[v] = Mn; return; }
    int pos = atomicAdd(&g_cnt[g], 1);
    int j = g * kk + pos;
    g_newpos[v] = j;
    g_gidx[j] = v;
    g_tanhv[j] = tanhf(sv);
}

// ---------------- gather: float out + fp16 splits for next gemm1 ----------------
__global__ void k_gather(const float* __restrict__ h, float* __restrict__ xnew, int Mn)
{
    int idx = blockIdx.x * blockDim.x + threadIdx.x;
    int j = idx >> 5, q = idx & 31;
    if (j >= Mn) return;
    float t = g_tanhv[j];
    float4 v = *(const float4*)(h + (size_t)g_gidx[j] * F + q * 4);
    v.x *= t; v.y *= t; v.z *= t; v.w *= t;
    *(float4*)(xnew + (size_t)j * F + q * 4) = v;
    __half h0, h1, h2, h3, l0, l1, l2, l3;
    split2(v.x, h0, l0); split2(v.y, h1, l1);
    split2(v.z, h2, l2); split2(v.w, h3, l3);
    __half2* oh = (__half2*)(g_xh + (size_t)j * F + q * 4);
    __half2* ol = (__half2*)(g_xl + (size_t)j * F + q * 4);
    oh[0] = __halves2half2(h0, h1); oh[1] = __halves2half2(h2, h3);
    ol[0] = __halves2half2(l0, l1); ol[1] = __halves2half2(l2, l3);
}

__global__ void k_remap(const int* __restrict__ es, const int* __restrict__ ed,
                        int* __restrict__ eo, int E, int Mn)
{
    int i = blockIdx.x * blockDim.x + threadIdx.x;
    if (i >= E) return;
    int s = g_newpos[es[i]];
    int d = g_newpos[ed[i]];
    if (s == Mn || d == Mn) { s = Mn; d = Mn; }
    eo[i] = s;
    eo[E + i] = d;
}

// ---------------- readout ----------------
__global__ void k_rpart(const float* __restrict__ x, int kk)
{
    int g = blockIdx.x / CH, c = blockIdx.x % CH;
    int rpc = kk / CH;
    int f = threadIdx.x;  // 128
    const float* base = x + ((size_t)g * kk + (size_t)c * rpc) * F + f;
    float vmax = -3.4e38f, vsum = 0.f;
    for (int r = 0; r < rpc; r++) {
        float v = base[(size_t)r * F];
        vmax = fmaxf(vmax, v);
        vsum += v;
    }
    float* p = g_part + (size_t)blockIdx.x * 2 * F;
    p[f] = vmax;
    p[F + f] = vsum;
}

__global__ void k_rfinal(int kk, int store)
{
    int g = blockIdx.x;
    int f = threadIdx.x;  // 256
    const float* p = g_part + (size_t)g * CH * 2 * F;
    float r;
    if (f < F) {
        float m = -3.4e38f;
        for (int c = 0; c < CH; c++) m = fmaxf(m, p[c * 2 * F + f]);
        r = m;
    } else {
        float s = 0.f;
        for (int c = 0; c < CH; c++) s += p[c * 2 * F + f];
        r = s / (float)kk;
    }
    if (store) g_z[g * 2 * F + f] = r;
    else       g_z[g * 2 * F + f] += r;
}

// ---------------- final MLP + sigmoid ----------------
__global__ void k_mlp(const float* __restrict__ Wl1, const float* __restrict__ bl1,
                      const float* __restrict__ Wl2, const float* __restrict__ bl2,
                      const float* __restrict__ Wl3, const float* __restrict__ bl3,
                      float* __restrict__ out)
{
    __shared__ float sz[BGR][2 * F];
    __shared__ float h1[BGR][F];
    __shared__ float h2[BGR][64];
    int t = threadIdx.x;  // 256
    for (int i = t; i < BGR * 2 * F; i += 256) ((float*)sz)[i] = g_z[i];
    __syncthreads();
    for (int o = t; o < BGR * F; o += 256) {
        int g = o >> 7, r = o & 127;
        float a = bl1[r];
        const float* wr = Wl1 + (size_t)r * 2 * F;
        for (int c = 0; c < 2 * F; c++) a += sz[g][c] * wr[c];
        h1[g][r] = fmaxf(a, 0.f);
    }
    __syncthreads();
    for (int o = t; o < BGR * 64; o += 256) {
        int g = o >> 6, r = o & 63;
        float a = bl2[r];
        const float* wr = Wl2 + (size_t)r * F;
        for (int c = 0; c < F; c++) a += h1[g][c] * wr[c];
        h2[g][r] = fmaxf(a, 0.f);
    }
    __syncthreads();
    if (t < BGR) {
        float a = bl3[0];
        for (int c = 0; c < 64; c++) a += h2[t][c] * Wl3[c];
        out[t] = 1.f / (1.f + expf(-a));
    }
}

// ---------------- orchestration (serial stream) ----------------
extern "C" void kernel_launch(void* const* d_in, const int* in_sizes, int n_in,
                              void* d_out, int out_size)
{
    const float* x = (const float*)d_in[0];
    const int* ei = (const int*)d_in[1];
    const float* Wlin[3] = { (const float*)d_in[2], (const float*)d_in[6], (const float*)d_in[10] };
    const float* blin[3] = { (const float*)d_in[3], (const float*)d_in[7], (const float*)d_in[11] };
    const float* Wupd[3] = { (const float*)d_in[4], (const float*)d_in[8], (const float*)d_in[12] };
    const float* wp[3]   = { (const float*)d_in[5], (const float*)d_in[9], (const float*)d_in[13] };
    const float* Wl1 = (const float*)d_in[14];
    const float* bl1 = (const float*)d_in[15];
    const float* Wl2 = (const float*)d_in[16];
    const float* bl2 = (const float*)d_in[17];
    const float* Wl3 = (const float*)d_in[18];
    const float* bl3 = (const float*)d_in[19];

    float *yb, *h1p, *h2p;
    __half *xh, *xl, *ah, *al, *w1h, *w1l, *w2h, *w2l;
    int *eA, *eB;
    cudaGetSymbolAddress((void**)&yb, g_y);
    cudaGetSymbolAddress((void**)&h1p, g_h1);
    cudaGetSymbolAddress((void**)&h2p, g_h2);
    cudaGetSymbolAddress((void**)&xh, g_xh);
    cudaGetSymbolAddress((void**)&xl, g_xl);
    cudaGetSymbolAddress((void**)&ah, g_ah);
    cudaGetSymbolAddress((void**)&al, g_al);
    cudaGetSymbolAddress((void**)&w1h, g_w1h);
    cudaGetSymbolAddress((void**)&w1l, g_w1l);
    cudaGetSymbolAddress((void**)&w2h, g_w2h);
    cudaGetSymbolAddress((void**)&w2l, g_w2l);
    cudaGetSymbolAddress((void**)&eA, g_eA);
    cudaGetSymbolAddress((void**)&eB, g_eB);

    static int init_done = 0;
    if (!init_done) {
        cudaFuncSetAttribute(k_gemm_h<1>, cudaFuncAttributeMaxDynamicSharedMemorySize, SMEM_H);
        cudaFuncSetAttribute(k_gemm_h<2>, cudaFuncAttributeMaxDynamicSharedMemorySize, SMEM_H);
        init_done = 1;
    }

    const int Ms[3] = { 100000, 80000, 64000 };
    const int kks[3] = { 10000, 8000, 6400 };

    const int* es = ei;
    const int* ed = ei + EMAX;

    k_split<<<(NMAX * F / 4 + 255) / 256, 256>>>(x, xh, xl, NMAX * F / 4);

    for (int st = 0; st < 3; ++st) {
        int M = Ms[st];
        int gridG = (M + 127) / 128;
        int kk = kks[st], n = M / BGR, Mn = BGR * kk;

        k_splitw<<<(128 * 384 / 4 + 255) / 256, 256>>>(Wlin[st], Wupd[st]);

        // SAGEConv
        k_gemm_h<1><<<gridG, 256, SMEM_H>>>(xh, xl, nullptr, nullptr, w1h, w1l, blin[st], yb, M);
        k_zerodeg<<<(M + 255) / 256, 256>>>(M);
        k_bucket<<<(EMAX / 2 + 255) / 256, 256>>>(es, ed, EMAX, M);
        k_aggr<<<(M + 7) / 8, 256>>>(yb, M);
        k_gemm_h<2><<<gridG, 256, SMEM_H>>>(ah, al, xh, xl, w2h, w2l, nullptr, h1p, M);

        // TopK pool
        k_scores<<<(M + 3) / 4, 128>>>(h1p, wp[st], M);
        k_select<<<BGR, 1024>>>(n, kk);
        k_compact<<<(M + 1 + 255) / 256, 256>>>(M, n, kk, Mn);
        k_gather<<<(Mn * 32 + 255) / 256, 256>>>(h1p, h2p, Mn);
        if (st < 2) {
            int* eo = (st == 0) ? eA : eB;
            k_remap<<<(EMAX + 255) / 256, 256>>>(es, ed, eo, EMAX, Mn);
            es = eo;
            ed = eo + EMAX;
        }

        // readout
        k_rpart<<<BGR * CH, 128>>>(h2p, kk);
        k_rfinal<<<BGR, 256>>>(kk, st == 0 ? 1 : 0);
    }

    k_mlp<<<1, 256>>>(Wl1, bl1, Wl2, bl2, Wl3, bl3, (float*)d_out);
}